// round 12
// baseline (speedup 1.0000x reference)
#include <cuda_runtime.h>
#include <cuda_bf16.h>
#include <cstdint>

#define EPC     64
#define NTH     512
#define NPH     4           // phases (16 e' each)
#define TPP     8           // tiles per phase (8 i each) ; K-tile = 128
#define NTILES  32

// smem layout (bytes)
#define OFF_S   0                   // 64 n * 81 float4 (1296 B) = 82944
#define S_F4STRIDE 81
#define OFF_A   82944               // [hi kh0 8K, hi kh1 8K, lo kh0 8K, lo kh1 8K] = 32768
#define OFF_B   115712              // [hi kh0 16K, hi kh1 16K, lo kh0 16K, lo kh1 16K] = 65536
#define SMEM_BYTES 181248

__device__ __align__(16) unsigned short g_Bhi[NTILES * 16384];
__device__ __align__(16) unsigned short g_Blo[NTILES * 16384];

__host__ __device__ __forceinline__ uint32_t swz(uint32_t o) { return o ^ ((o >> 3) & 0x70u); }

__device__ __forceinline__ uint32_t smem_u32(const void* p) {
    uint32_t a;
    asm("{ .reg .u64 t; cvta.to.shared.u64 t, %1; cvt.u32.u64 %0, t; }" : "=r"(a) : "l"(p));
    return a;
}
__device__ __forceinline__ unsigned long long pk2(float x, float y) {
    unsigned long long u; asm("mov.b64 %0, {%1,%2};" : "=l"(u) : "f"(x), "f"(y)); return u;
}
__device__ __forceinline__ void upk2(unsigned long long u, float& x, float& y) {
    asm("mov.b64 {%0,%1}, %2;" : "=f"(x), "=f"(y) : "l"(u));
}
#define FMA2(d, a, b) asm("fma.rn.f32x2 %0, %1, %2, %0;" : "+l"(d) : "l"(a), "l"(b))

__device__ __forceinline__ void ldsm4(uint32_t& r0, uint32_t& r1, uint32_t& r2, uint32_t& r3,
                                      uint32_t addr) {
    asm volatile("ldmatrix.sync.aligned.m8n8.x4.shared.b16 {%0,%1,%2,%3}, [%4];"
                 : "=r"(r0), "=r"(r1), "=r"(r2), "=r"(r3) : "r"(addr));
}
__device__ __forceinline__ void mma16816(float* c, uint32_t a0, uint32_t a1, uint32_t a2,
                                         uint32_t a3, uint32_t b0, uint32_t b1) {
    asm volatile("mma.sync.aligned.m16n8k16.row.col.f32.bf16.bf16.f32 "
                 "{%0,%1,%2,%3}, {%4,%5,%6,%7}, {%8,%9}, {%0,%1,%2,%3};"
                 : "+f"(c[0]), "+f"(c[1]), "+f"(c[2]), "+f"(c[3])
                 : "r"(a0), "r"(a1), "r"(a2), "r"(a3), "r"(b0), "r"(b1));
}
__device__ __forceinline__ uint32_t bf2(float hi, float lo) {
    uint32_t w;
    asm("cvt.rn.bf16x2.f32 %0, %1, %2;" : "=r"(w) : "f"(hi), "f"(lo));
    return w;
}

// ---------- prep: split W into hi/lo bf16, tile + SW128 pre-swizzle ----------
// tile tg = p*8 + ti covers i = ti*8..+7, e = p*16..+15; kk = (i_local)*16 + e''
// per-tile layout: [kh (kk>>6)][u 128 rows][64 k swizzled 128B rows]
__global__ void prep_B(const float* __restrict__ W) {
    int idx = blockIdx.x * blockDim.x + threadIdx.x;
    if (idx >= NTILES * 8192) return;
    int t = idx >> 13, r = idx & 8191;
    int kh = r >> 12, rr = r & 4095;
    int u = rr >> 5, kp = rr & 31;
    int p = t >> 3, ti = t & 7;
    uint32_t hi = 0, lo = 0;
    #pragma unroll
    for (int d = 0; d < 2; d++) {
        int kk = kh * 64 + kp * 2 + d;
        int i = ti * 8 + (kk >> 4);
        int e = p * 16 + (kk & 15);
        float v = W[((e << 6) + i) * 128 + u];
        __nv_bfloat16 h = __float2bfloat16_rn(v);
        float hf = __bfloat162float(h);
        __nv_bfloat16 l = __float2bfloat16_rn(v - hf);
        hi |= (uint32_t)(*(unsigned short*)&h) << (16 * d);
        lo |= (uint32_t)(*(unsigned short*)&l) << (16 * d);
    }
    uint32_t pos = (uint32_t)kh * 4096 + (swz((uint32_t)(u * 128 + kp * 4)) >> 2);
    ((uint32_t*)g_Bhi)[(long)t * 8192 + pos] = hi;
    ((uint32_t*)g_Blo)[(long)t * 8192 + pos] = lo;
}

// ---------- main ----------
__global__ __launch_bounds__(NTH, 1)
void eib_mma(const float* __restrict__ rbf,   // [NE][64][16]
             const float* __restrict__ sph,   // [NE][16][16]
             const float* __restrict__ m,     // [NE*8][64]
             float* __restrict__ out,         // [NE][128]
             int nEdges)
{
    extern __shared__ char smem[];
    const uint32_t sb = smem_u32(smem);
    float4* S4 = (float4*)smem;
    const int tid = threadIdx.x, wid = tid >> 5, lane = tid & 31;
    const int e0 = blockIdx.x * EPC;

    // consumer warp tiling: wm (32 n rows), wn (32 u), kh (K-half of 64)
    const int wm = wid >> 3, wn = (wid >> 1) & 3, kh = wid & 1;

    float acc[2][4][4];
    #pragma unroll
    for (int mf = 0; mf < 2; mf++)
        #pragma unroll
        for (int ub = 0; ub < 4; ub++)
            #pragma unroll
            for (int c = 0; c < 4; c++) acc[mf][ub][c] = 0.f;

    // A-gen mapping
    const int agn = tid >> 3, agq = tid & 7;
    const int e_ag = e0 + agn;
    const int akh = agq >> 2, aqq = agq & 3;

    for (int p = 0; p < NPH; p++) {
        // ======== S build: S[n][s][e''(16)] ; rows r = tid, tid+512 ========
        #pragma unroll
        for (int rr = 0; rr < 2; rr++) {
            int r = tid + rr * NTH;
            int n = r >> 4, s = r & 15;
            int e = e0 + n;
            unsigned long long a2[8];
            #pragma unroll
            for (int c = 0; c < 8; c++) a2[c] = 0ull;
            if (e < nEdges) {
                const float4* sp4 = (const float4*)sph + ((long)e * 16 + s) * 4;
                float4 sA = sp4[0], sB = sp4[1];          // k = 0..7
                const float4* mbase = (const float4*)m + ((long)e * 8) * 16 + p * 4;
                #pragma unroll
                for (int k = 0; k < 8; k++) {
                    float sv = (k < 4) ? (&sA.x)[k] : (&sB.x)[k - 4];
                    unsigned long long sk = pk2(sv, sv);
                    const float4* mrow = mbase + (long)k * 16;
                    #pragma unroll
                    for (int c4 = 0; c4 < 4; c4++) {
                        float4 mv = mrow[c4];
                        FMA2(a2[c4 * 2],     sk, pk2(mv.x, mv.y));
                        FMA2(a2[c4 * 2 + 1], sk, pk2(mv.z, mv.w));
                    }
                }
            }
            float4* Srow = S4 + n * S_F4STRIDE + s * 5;
            #pragma unroll
            for (int c4 = 0; c4 < 4; c4++) {
                float4 v;
                upk2(a2[c4 * 2], v.x, v.y);
                upk2(a2[c4 * 2 + 1], v.z, v.w);
                Srow[c4] = v;
            }
        }
        __syncthreads();

        // ======== 8 K-tiles (8 i's x 16 e' each) ========
        for (int ti = 0; ti < TPP; ti++) {
            int tg = p * TPP + ti;
            int i0 = ti * 8;

            // ---- A-gen: thread (agn, agq): i = i0+agq, e'' = 0..15 ----
            {
                float4 rv[4];
                if (e_ag < nEdges) {
                    const float4* rp = (const float4*)rbf + ((long)e_ag * 64 + i0 + agq) * 4;
                    rv[0] = rp[0]; rv[1] = rp[1]; rv[2] = rp[2]; rv[3] = rp[3];
                } else {
                    rv[0] = rv[1] = rv[2] = rv[3] = make_float4(0.f, 0.f, 0.f, 0.f);
                }
                unsigned long long a2[8];
                #pragma unroll
                for (int c = 0; c < 8; c++) a2[c] = 0ull;
                const ulonglong2* Sn = (const ulonglong2*)(S4 + agn * S_F4STRIDE);
                #pragma unroll
                for (int s = 0; s < 16; s++) {
                    float rb = (&rv[s >> 2].x)[s & 3];
                    unsigned long long rr2 = pk2(rb, rb);
                    #pragma unroll
                    for (int c = 0; c < 4; c++) {
                        ulonglong2 mv = Sn[s * 5 + c];
                        FMA2(a2[c * 2],     rr2, mv.x);
                        FMA2(a2[c * 2 + 1], rr2, mv.y);
                    }
                }
                float f[16];
                #pragma unroll
                for (int c = 0; c < 8; c++) upk2(a2[c], f[2 * c], f[2 * c + 1]);
                uint32_t hiw[8], low[8];
                #pragma unroll
                for (int j = 0; j < 8; j++) {
                    hiw[j] = bf2(f[2 * j + 1], f[2 * j]);
                    float g0 = __uint_as_float(hiw[j] << 16);
                    float g1 = __uint_as_float(hiw[j] & 0xFFFF0000u);
                    low[j] = bf2(f[2 * j + 1] - g1, f[2 * j] - g0);
                }
                // o is 32-aligned; second 16B unit lives at swz(o)^16 (NOT swz(o)+16):
                // SW128 XORs addr bits[4:6] with bits[7:9], so within a 32B pair the
                // two 16B units swap when bit7 of o (agn&1) is set.
                uint32_t so  = swz((uint32_t)(agn * 128 + aqq * 32));
                uint32_t so2 = so ^ 16u;
                uint32_t base = (uint32_t)(OFF_A + akh * 8192);
                *(uint4*)(smem + base + so)  = make_uint4(hiw[0], hiw[1], hiw[2], hiw[3]);
                *(uint4*)(smem + base + so2) = make_uint4(hiw[4], hiw[5], hiw[6], hiw[7]);
                *(uint4*)(smem + base + 16384 + so)  = make_uint4(low[0], low[1], low[2], low[3]);
                *(uint4*)(smem + base + 16384 + so2) = make_uint4(low[4], low[5], low[6], low[7]);
            }
            // ---- B copy (pre-swizzled, verbatim): 2048 f4 per half ----
            {
                const float4* bh = (const float4*)g_Bhi + (long)tg * 2048;
                const float4* bl = (const float4*)g_Blo + (long)tg * 2048;
                float4* dh = (float4*)(smem + OFF_B);
                float4* dl = (float4*)(smem + OFF_B + 32768);
                #pragma unroll
                for (int c = 0; c < 4; c++) {
                    int f = tid + c * NTH;
                    dh[f] = bh[f];
                    dl[f] = bl[f];
                }
            }
            __syncthreads();

            // ---- consumer: ldmatrix + mma (warp's K-half kh) ----
            {
                const int t = lane >> 3, rw = lane & 7;
                const uint32_t aregH = (uint32_t)(OFF_A + kh * 8192);
                const uint32_t aregL = aregH + 16384u;
                const uint32_t bregH = (uint32_t)(OFF_B + kh * 16384);
                const uint32_t bregL = bregH + 32768u;
                const int urow0 = wn * 32 + (t & 1) * 8 + rw;
                #pragma unroll
                for (int ks = 0; ks < 4; ks++) {
                    uint32_t chunk = (uint32_t)(ks * 32 + (t >> 1) * 16);
                    uint32_t ah[2][4], al[2][4], bh[8], bl[8];
                    #pragma unroll
                    for (int mf = 0; mf < 2; mf++) {
                        uint32_t abyte = swz((uint32_t)((wm * 32 + mf * 16 + (t & 1) * 8 + rw) * 128) + chunk);
                        ldsm4(ah[mf][0], ah[mf][1], ah[mf][2], ah[mf][3], sb + aregH + abyte);
                        ldsm4(al[mf][0], al[mf][1], al[mf][2], al[mf][3], sb + aregL + abyte);
                    }
                    uint32_t b0byte = swz((uint32_t)(urow0 * 128) + chunk);
                    uint32_t b1byte = swz((uint32_t)((urow0 + 16) * 128) + chunk);
                    ldsm4(bh[0], bh[1], bh[2], bh[3], sb + bregH + b0byte);
                    ldsm4(bh[4], bh[5], bh[6], bh[7], sb + bregH + b1byte);
                    ldsm4(bl[0], bl[1], bl[2], bl[3], sb + bregL + b0byte);
                    ldsm4(bl[4], bl[5], bl[6], bl[7], sb + bregL + b1byte);
                    #pragma unroll
                    for (int mf = 0; mf < 2; mf++)
                        #pragma unroll
                        for (int ub = 0; ub < 4; ub++) {
                            int base = (ub >> 1) * 4 + (ub & 1);
                            mma16816(acc[mf][ub], ah[mf][0], ah[mf][1], ah[mf][2], ah[mf][3],
                                     bh[base], bh[base + 2]);
                            mma16816(acc[mf][ub], ah[mf][0], ah[mf][1], ah[mf][2], ah[mf][3],
                                     bl[base], bl[base + 2]);
                            mma16816(acc[mf][ub], al[mf][0], al[mf][1], al[mf][2], al[mf][3],
                                     bh[base], bh[base + 2]);
                        }
                }
            }
            __syncthreads();
        }
    }

    // ======== kh-reduction + epilogue ========
    {
        int ridx = wm * 4 + wn;
        if (kh == 1) {
            #pragma unroll
            for (int mf = 0; mf < 2; mf++)
                #pragma unroll
                for (int ub = 0; ub < 4; ub++)
                    *(float4*)(smem + OFF_B + ridx * 4096 + (mf * 4 + ub) * 512 + lane * 16) =
                        make_float4(acc[mf][ub][0], acc[mf][ub][1], acc[mf][ub][2], acc[mf][ub][3]);
        }
        __syncthreads();
        if (kh == 0) {
            int gid = lane >> 2, tig = lane & 3;
            #pragma unroll
            for (int mf = 0; mf < 2; mf++) {
                int e1 = e0 + wm * 32 + mf * 16 + gid;
                int e2 = e1 + 8;
                #pragma unroll
                for (int ub = 0; ub < 4; ub++) {
                    float4 o = *(float4*)(smem + OFF_B + ridx * 4096 + (mf * 4 + ub) * 512 + lane * 16);
                    int u = wn * 32 + ub * 8 + tig * 2;
                    if (e1 < nEdges)
                        *(float2*)(out + (long)e1 * 128 + u) =
                            make_float2(acc[mf][ub][0] + o.x, acc[mf][ub][1] + o.y);
                    if (e2 < nEdges)
                        *(float2*)(out + (long)e2 * 128 + u) =
                            make_float2(acc[mf][ub][2] + o.z, acc[mf][ub][3] + o.w);
                }
            }
        }
    }
}

extern "C" void kernel_launch(void* const* d_in, const int* in_sizes, int n_in,
                              void* d_out, int out_size)
{
    const float* rbf = (const float*)d_in[0];
    const float* sph = (const float*)d_in[1];
    const float* m   = (const float*)d_in[2];
    const float* W   = (const float*)d_in[3];
    float* out = (float*)d_out;

    int nEdges = in_sizes[0] / (64 * 16);   // 50000

    cudaFuncSetAttribute(eib_mma, cudaFuncAttributeMaxDynamicSharedMemorySize, SMEM_BYTES);

    prep_B<<<NTILES * 8192 / 256, 256>>>(W);
    int grid = (nEdges + EPC - 1) / EPC;    // 782
    eib_mma<<<grid, NTH, SMEM_BYTES>>>(rbf, sph, m, out, nEdges);
}

// round 13
// speedup vs baseline: 1.0604x; 1.0604x over previous
#include <cuda_runtime.h>
#include <cuda_bf16.h>
#include <cstdint>

#define EPC     64
#define NTH     512
#define NPH     4           // phases (16 e' each)
#define TPP     8           // tiles per phase (8 i each); K-tile = 128
#define NTILES  32

// smem layout (bytes)
#define OFF_S   0                   // 64 n * 81 float4 = 82944
#define S_F4STRIDE 81
#define OFF_A   82944               // 2 bufs x [hi kh0 8K | hi kh1 8K | lo kh0 8K | lo kh1 8K]
#define SMEM_BYTES 148480

// B fragments, mma-ready per-lane order: [tile][g(16 u8-groups)][ks(8)][lane(32)]
// uint4 = {bh0, bh1, bl0, bl1}
__device__ __align__(16) uint4 g_Bf[NTILES * 16 * 8 * 32];

__host__ __device__ __forceinline__ uint32_t swz(uint32_t o) { return o ^ ((o >> 3) & 0x70u); }

__device__ __forceinline__ uint32_t smem_u32(const void* p) {
    uint32_t a;
    asm("{ .reg .u64 t; cvta.to.shared.u64 t, %1; cvt.u32.u64 %0, t; }" : "=r"(a) : "l"(p));
    return a;
}
__device__ __forceinline__ unsigned long long pk2(float x, float y) {
    unsigned long long u; asm("mov.b64 %0, {%1,%2};" : "=l"(u) : "f"(x), "f"(y)); return u;
}
__device__ __forceinline__ void upk2(unsigned long long u, float& x, float& y) {
    asm("mov.b64 {%0,%1}, %2;" : "=f"(x), "=f"(y) : "l"(u));
}
#define FMA2(d, a, b) asm("fma.rn.f32x2 %0, %1, %2, %0;" : "+l"(d) : "l"(a), "l"(b))

__device__ __forceinline__ void ldsm4(uint32_t& r0, uint32_t& r1, uint32_t& r2, uint32_t& r3,
                                      uint32_t addr) {
    asm volatile("ldmatrix.sync.aligned.m8n8.x4.shared.b16 {%0,%1,%2,%3}, [%4];"
                 : "=r"(r0), "=r"(r1), "=r"(r2), "=r"(r3) : "r"(addr));
}
__device__ __forceinline__ void mma16816(float* c, uint32_t a0, uint32_t a1, uint32_t a2,
                                         uint32_t a3, uint32_t b0, uint32_t b1) {
    asm volatile("mma.sync.aligned.m16n8k16.row.col.f32.bf16.bf16.f32 "
                 "{%0,%1,%2,%3}, {%4,%5,%6,%7}, {%8,%9}, {%0,%1,%2,%3};"
                 : "+f"(c[0]), "+f"(c[1]), "+f"(c[2]), "+f"(c[3])
                 : "r"(a0), "r"(a1), "r"(a2), "r"(a3), "r"(b0), "r"(b1));
}
__device__ __forceinline__ uint32_t bf2(float hi, float lo) {
    uint32_t w;
    asm("cvt.rn.bf16x2.f32 %0, %1, %2;" : "=r"(w) : "f"(hi), "f"(lo));
    return w;
}

// ---------- prep: self-calibrating B fragment factory ----------
// Stages each (tile, kh) W half in smem exactly like R12's B region, runs R12's
// exact ldmatrix sequence, stores resulting per-lane frags linearly to gmem.
__global__ void prep_B(const float* __restrict__ W) {
    __shared__ __align__(16) char bs[32768];     // [hi 16K][lo 16K], 128 u-rows x 128B
    const int tile = blockIdx.x, kh = blockIdx.y;
    const int p = tile >> 3, ti = tile & 7;
    const int tid = threadIdx.x;                 // 128 threads

    for (int j = tid; j < 128 * 32; j += 128) {
        int u = j >> 5, kp = j & 31;
        uint32_t hi = 0, lo = 0;
        #pragma unroll
        for (int d = 0; d < 2; d++) {
            int kk = kh * 64 + kp * 2 + d;       // kk = i_local*16 + e''
            int i = ti * 8 + (kk >> 4);
            int e = p * 16 + (kk & 15);
            float v = W[((e << 6) + i) * 128 + u];
            __nv_bfloat16 h = __float2bfloat16_rn(v);
            __nv_bfloat16 l = __float2bfloat16_rn(v - __bfloat162float(h));
            hi |= (uint32_t)(*(unsigned short*)&h) << (16 * d);
            lo |= (uint32_t)(*(unsigned short*)&l) << (16 * d);
        }
        uint32_t pos = swz((uint32_t)(u * 128 + kp * 4));
        *(uint32_t*)(bs + pos) = hi;
        *(uint32_t*)(bs + 16384 + pos) = lo;
    }
    __syncthreads();

    const int wn = tid >> 5, lane = tid & 31;
    const uint32_t sbb = smem_u32(bs);
    const int t = lane >> 3, rw = lane & 7;
    const int urow0 = wn * 32 + (t & 1) * 8 + rw;
    for (int ks = 0; ks < 4; ks++) {
        uint32_t chunk = (uint32_t)(ks * 32 + (t >> 1) * 16);
        uint32_t b0byte = swz((uint32_t)(urow0 * 128) + chunk);
        uint32_t b1byte = swz((uint32_t)((urow0 + 16) * 128) + chunk);
        uint32_t bh[8], bl[8];
        ldsm4(bh[0], bh[1], bh[2], bh[3], sbb + b0byte);
        ldsm4(bh[4], bh[5], bh[6], bh[7], sbb + b1byte);
        ldsm4(bl[0], bl[1], bl[2], bl[3], sbb + 16384 + b0byte);
        ldsm4(bl[4], bl[5], bl[6], bl[7], sbb + 16384 + b1byte);
        #pragma unroll
        for (int ub = 0; ub < 4; ub++) {
            int base = (ub >> 1) * 4 + (ub & 1);
            int g = wn * 4 + ub;                 // u8-group: u = g*8..g*8+7
            int oidx = (((tile * 16 + g) * 8) + (kh * 4 + ks)) * 32 + lane;
            g_Bf[oidx] = make_uint4(bh[base], bh[base + 2], bl[base], bl[base + 2]);
        }
    }
}

// ---------- main ----------
__global__ __launch_bounds__(NTH, 1)
void eib_mma(const float* __restrict__ rbf,   // [NE][64][16]
             const float* __restrict__ sph,   // [NE][16][16]
             const float* __restrict__ m,     // [NE*8][64]
             float* __restrict__ out,         // [NE][128]
             int nEdges)
{
    extern __shared__ char smem[];
    const uint32_t sb = smem_u32(smem);
    float4* S4 = (float4*)smem;
    const int tid = threadIdx.x, wid = tid >> 5, lane = tid & 31;
    const int e0 = blockIdx.x * EPC;

    float acc[4][4];
    #pragma unroll
    for (int mf = 0; mf < 4; mf++)
        #pragma unroll
        for (int c = 0; c < 4; c++) acc[mf][c] = 0.f;

    // A-gen mapping: thread (agn edge-row, agq = i_local)
    const int agn = tid >> 3, agq = tid & 7;
    const int e_ag = e0 + agn;
    const int akh = agq >> 2, aqq = agq & 3;
    // consumer lane geometry
    const int ct = lane >> 3, crw = lane & 7;

    int tg = 0;
    for (int p = 0; p < NPH; p++) {
        // ======== S build: S[n][s][e''(16)] ; rows r = tid, tid+512 ========
        // (safe vs laggard consumers: they read only A bufs + B regs)
        #pragma unroll
        for (int rr = 0; rr < 2; rr++) {
            int r = tid + rr * NTH;
            int n = r >> 4, s = r & 15;
            int e = e0 + n;
            unsigned long long a2[8];
            #pragma unroll
            for (int c = 0; c < 8; c++) a2[c] = 0ull;
            if (e < nEdges) {
                const float4* sp4 = (const float4*)sph + ((long)e * 16 + s) * 4;
                float4 sA = sp4[0], sB = sp4[1];          // k = 0..7
                const float4* mbase = (const float4*)m + ((long)e * 8) * 16 + p * 4;
                #pragma unroll
                for (int k = 0; k < 8; k++) {
                    float sv = (k < 4) ? (&sA.x)[k] : (&sB.x)[k - 4];
                    unsigned long long sk = pk2(sv, sv);
                    const float4* mrow = mbase + (long)k * 16;
                    #pragma unroll
                    for (int c4 = 0; c4 < 4; c4++) {
                        float4 mv = mrow[c4];
                        FMA2(a2[c4 * 2],     sk, pk2(mv.x, mv.y));
                        FMA2(a2[c4 * 2 + 1], sk, pk2(mv.z, mv.w));
                    }
                }
            }
            float4* Srow = S4 + n * S_F4STRIDE + s * 5;
            #pragma unroll
            for (int c4 = 0; c4 < 4; c4++) {
                float4 v;
                upk2(a2[c4 * 2], v.x, v.y);
                upk2(a2[c4 * 2 + 1], v.z, v.w);
                Srow[c4] = v;
            }
        }
        __syncthreads();

        // ======== 8 K-tiles (8 i x 16 e' each), single-barrier pipeline ========
        for (int ti = 0; ti < TPP; ti++, tg++) {
            const int buf = tg & 1;
            const uint32_t ABASE = (uint32_t)(OFF_A + buf * 32768);
            const int i0 = ti * 8;

            // ---- B prefetch (consumed after the barrier; latency hidden by gen) ----
            uint4 Bv[8];
            {
                const uint4* bp = g_Bf + ((tg * 16 + wid) * 8) * 32 + lane;
                #pragma unroll
                for (int ks = 0; ks < 8; ks++) Bv[ks] = bp[ks * 32];
            }

            // ---- A-gen into buf (R12-proven math) ----
            {
                float4 rv[4];
                if (e_ag < nEdges) {
                    const float4* rp = (const float4*)rbf + ((long)e_ag * 64 + i0 + agq) * 4;
                    rv[0] = rp[0]; rv[1] = rp[1]; rv[2] = rp[2]; rv[3] = rp[3];
                } else {
                    rv[0] = rv[1] = rv[2] = rv[3] = make_float4(0.f, 0.f, 0.f, 0.f);
                }
                unsigned long long a2[8];
                #pragma unroll
                for (int c = 0; c < 8; c++) a2[c] = 0ull;
                const ulonglong2* Sn = (const ulonglong2*)(S4 + agn * S_F4STRIDE);
                #pragma unroll
                for (int s = 0; s < 16; s++) {
                    float rb = (&rv[s >> 2].x)[s & 3];
                    unsigned long long rr2 = pk2(rb, rb);
                    #pragma unroll
                    for (int c = 0; c < 4; c++) {
                        ulonglong2 mv = Sn[s * 5 + c];
                        FMA2(a2[c * 2],     rr2, mv.x);
                        FMA2(a2[c * 2 + 1], rr2, mv.y);
                    }
                }
                float f[16];
                #pragma unroll
                for (int c = 0; c < 8; c++) upk2(a2[c], f[2 * c], f[2 * c + 1]);
                uint32_t hiw[8], low[8];
                #pragma unroll
                for (int j = 0; j < 8; j++) {
                    hiw[j] = bf2(f[2 * j + 1], f[2 * j]);
                    float g0 = __uint_as_float(hiw[j] << 16);
                    float g1 = __uint_as_float(hiw[j] & 0xFFFF0000u);
                    low[j] = bf2(f[2 * j + 1] - g1, f[2 * j] - g0);
                }
                // 32B store pair: second 16B unit at swz(o)^16 (32-aligned o)
                uint32_t so  = swz((uint32_t)(agn * 128 + aqq * 32));
                uint32_t so2 = so ^ 16u;
                uint32_t base = ABASE + (uint32_t)(akh * 8192);
                *(uint4*)(smem + base + so)  = make_uint4(hiw[0], hiw[1], hiw[2], hiw[3]);
                *(uint4*)(smem + base + so2) = make_uint4(hiw[4], hiw[5], hiw[6], hiw[7]);
                *(uint4*)(smem + base + 16384 + so)  = make_uint4(low[0], low[1], low[2], low[3]);
                *(uint4*)(smem + base + 16384 + so2) = make_uint4(low[4], low[5], low[6], low[7]);
            }
            __syncthreads();   // the ONLY barrier per tile: A(buf) ready

            // ---- consumer: warp wid owns u = wid*8..+7, all 64 n, full K ----
            #pragma unroll
            for (int ks = 0; ks < 8; ks++) {
                const uint32_t areg = ABASE + (uint32_t)((ks >> 2) * 8192);
                const uint32_t chunk = (uint32_t)((ks & 3) * 32 + (ct >> 1) * 16);
                const uint4 B = Bv[ks];
                #pragma unroll
                for (int mf = 0; mf < 4; mf++) {
                    uint32_t abyte = swz((uint32_t)((mf * 16 + (ct & 1) * 8 + crw) * 128) + chunk);
                    uint32_t ah0, ah1, ah2, ah3, al0, al1, al2, al3;
                    ldsm4(ah0, ah1, ah2, ah3, sb + areg + abyte);
                    ldsm4(al0, al1, al2, al3, sb + areg + 16384 + abyte);
                    mma16816(acc[mf], ah0, ah1, ah2, ah3, B.x, B.y);   // hi*hi
                    mma16816(acc[mf], ah0, ah1, ah2, ah3, B.z, B.w);   // hi*lo
                    mma16816(acc[mf], al0, al1, al2, al3, B.x, B.y);   // lo*hi
                }
            }
        }
    }

    // ======== epilogue (registers only; no barrier needed) ========
    {
        const int gid = lane >> 2, tig = lane & 3;
        const int u = wid * 8 + tig * 2;
        #pragma unroll
        for (int mf = 0; mf < 4; mf++) {
            int e1 = e0 + mf * 16 + gid;
            int e2 = e1 + 8;
            if (e1 < nEdges)
                *(float2*)(out + (long)e1 * 128 + u) = make_float2(acc[mf][0], acc[mf][1]);
            if (e2 < nEdges)
                *(float2*)(out + (long)e2 * 128 + u) = make_float2(acc[mf][2], acc[mf][3]);
        }
    }
}

extern "C" void kernel_launch(void* const* d_in, const int* in_sizes, int n_in,
                              void* d_out, int out_size)
{
    const float* rbf = (const float*)d_in[0];
    const float* sph = (const float*)d_in[1];
    const float* m   = (const float*)d_in[2];
    const float* W   = (const float*)d_in[3];
    float* out = (float*)d_out;

    int nEdges = in_sizes[0] / (64 * 16);   // 50000

    cudaFuncSetAttribute(eib_mma, cudaFuncAttributeMaxDynamicSharedMemorySize, SMEM_BYTES);

    prep_B<<<dim3(NTILES, 2), 128>>>(W);
    int grid = (nEdges + EPC - 1) / EPC;    // 782
    eib_mma<<<grid, NTH, SMEM_BYTES>>>(rbf, sph, m, out, nEdges);
}

// round 14
// speedup vs baseline: 1.3971x; 1.3175x over previous
#include <cuda_runtime.h>
#include <cuda_bf16.h>
#include <cstdint>

#define EPC     32
#define NTH     256
#define NPH     4           // phases (16 e' each)
#define TPP     8           // tiles per phase (8 i each); K-tile = 128
#define NTILES  32

// smem layout (bytes)
#define OFF_S   0                   // 32 n * 81 float4 = 41472
#define S_F4STRIDE 81
#define OFF_A   41472               // 2 bufs x [hi: kh0 4K | kh1 4K][lo: kh0 | kh1] = 2 x 16384
#define SMEM_BYTES 74240

// B fragments, mma-ready per-lane order: [tile][g(16 u8-groups)][ks(8)][lane(32)]
// uint4 = {bh0, bh1, bl0, bl1}
__device__ __align__(16) uint4 g_Bf[NTILES * 16 * 8 * 32];

__host__ __device__ __forceinline__ uint32_t swz(uint32_t o) { return o ^ ((o >> 3) & 0x70u); }

__device__ __forceinline__ uint32_t smem_u32(const void* p) {
    uint32_t a;
    asm("{ .reg .u64 t; cvta.to.shared.u64 t, %1; cvt.u32.u64 %0, t; }" : "=r"(a) : "l"(p));
    return a;
}
__device__ __forceinline__ unsigned long long pk2(float x, float y) {
    unsigned long long u; asm("mov.b64 %0, {%1,%2};" : "=l"(u) : "f"(x), "f"(y)); return u;
}
__device__ __forceinline__ void upk2(unsigned long long u, float& x, float& y) {
    asm("mov.b64 {%0,%1}, %2;" : "=f"(x), "=f"(y) : "l"(u));
}
#define FMA2(d, a, b) asm("fma.rn.f32x2 %0, %1, %2, %0;" : "+l"(d) : "l"(a), "l"(b))

__device__ __forceinline__ void ldsm4(uint32_t& r0, uint32_t& r1, uint32_t& r2, uint32_t& r3,
                                      uint32_t addr) {
    asm volatile("ldmatrix.sync.aligned.m8n8.x4.shared.b16 {%0,%1,%2,%3}, [%4];"
                 : "=r"(r0), "=r"(r1), "=r"(r2), "=r"(r3) : "r"(addr));
}
__device__ __forceinline__ void mma16816(float* c, uint32_t a0, uint32_t a1, uint32_t a2,
                                         uint32_t a3, uint32_t b0, uint32_t b1) {
    asm volatile("mma.sync.aligned.m16n8k16.row.col.f32.bf16.bf16.f32 "
                 "{%0,%1,%2,%3}, {%4,%5,%6,%7}, {%8,%9}, {%0,%1,%2,%3};"
                 : "+f"(c[0]), "+f"(c[1]), "+f"(c[2]), "+f"(c[3])
                 : "r"(a0), "r"(a1), "r"(a2), "r"(a3), "r"(b0), "r"(b1));
}
__device__ __forceinline__ uint32_t bf2(float hi, float lo) {
    uint32_t w;
    asm("cvt.rn.bf16x2.f32 %0, %1, %2;" : "=r"(w) : "f"(hi), "f"(lo));
    return w;
}

// ---------- prep: self-calibrating B fragment factory (unchanged from R13, passed) ----------
__global__ void prep_B(const float* __restrict__ W) {
    __shared__ __align__(16) char bs[32768];     // [hi 16K][lo 16K], 128 u-rows x 128B
    const int tile = blockIdx.x, kh = blockIdx.y;
    const int p = tile >> 3, ti = tile & 7;
    const int tid = threadIdx.x;                 // 128 threads

    for (int j = tid; j < 128 * 32; j += 128) {
        int u = j >> 5, kp = j & 31;
        uint32_t hi = 0, lo = 0;
        #pragma unroll
        for (int d = 0; d < 2; d++) {
            int kk = kh * 64 + kp * 2 + d;       // kk = i_local*16 + e''
            int i = ti * 8 + (kk >> 4);
            int e = p * 16 + (kk & 15);
            float v = W[((e << 6) + i) * 128 + u];
            __nv_bfloat16 h = __float2bfloat16_rn(v);
            __nv_bfloat16 l = __float2bfloat16_rn(v - __bfloat162float(h));
            hi |= (uint32_t)(*(unsigned short*)&h) << (16 * d);
            lo |= (uint32_t)(*(unsigned short*)&l) << (16 * d);
        }
        uint32_t pos = swz((uint32_t)(u * 128 + kp * 4));
        *(uint32_t*)(bs + pos) = hi;
        *(uint32_t*)(bs + 16384 + pos) = lo;
    }
    __syncthreads();

    const int wn = tid >> 5, lane = tid & 31;
    const uint32_t sbb = smem_u32(bs);
    const int t = lane >> 3, rw = lane & 7;
    const int urow0 = wn * 32 + (t & 1) * 8 + rw;
    for (int ks = 0; ks < 4; ks++) {
        uint32_t chunk = (uint32_t)(ks * 32 + (t >> 1) * 16);
        uint32_t b0byte = swz((uint32_t)(urow0 * 128) + chunk);
        uint32_t b1byte = swz((uint32_t)((urow0 + 16) * 128) + chunk);
        uint32_t bh[8], bl[8];
        ldsm4(bh[0], bh[1], bh[2], bh[3], sbb + b0byte);
        ldsm4(bh[4], bh[5], bh[6], bh[7], sbb + b1byte);
        ldsm4(bl[0], bl[1], bl[2], bl[3], sbb + 16384 + b0byte);
        ldsm4(bl[4], bl[5], bl[6], bl[7], sbb + 16384 + b1byte);
        #pragma unroll
        for (int ub = 0; ub < 4; ub++) {
            int base = (ub >> 1) * 4 + (ub & 1);
            int g = wn * 4 + ub;                 // u8-group: u = g*8..g*8+7
            int oidx = (((tile * 16 + g) * 8) + (kh * 4 + ks)) * 32 + lane;
            g_Bf[oidx] = make_uint4(bh[base], bh[base + 2], bl[base], bl[base + 2]);
        }
    }
}

// ---------- main ----------
__global__ __launch_bounds__(NTH, 2)
void eib_mma(const float* __restrict__ rbf,   // [NE][64][16]
             const float* __restrict__ sph,   // [NE][16][16]
             const float* __restrict__ m,     // [NE*8][64]
             float* __restrict__ out,         // [NE][128]
             int nEdges)
{
    extern __shared__ char smem[];
    const uint32_t sb = smem_u32(smem);
    float4* S4 = (float4*)smem;
    const int tid = threadIdx.x, wid = tid >> 5, lane = tid & 31;
    const int e0 = blockIdx.x * EPC;

    float acc[2][2][4];                            // [mf 16n][ug 8u][frag]
    #pragma unroll
    for (int mf = 0; mf < 2; mf++)
        #pragma unroll
        for (int ug = 0; ug < 2; ug++)
            #pragma unroll
            for (int c = 0; c < 4; c++) acc[mf][ug][c] = 0.f;

    // A-gen mapping: thread = (agn edge-row, i2 i-pair, eh e'-half)
    const int agn = tid >> 3;                      // 0..31
    const int i2 = tid & 3, eh = (tid >> 2) & 1;
    const int e_ag = e0 + agn;
    // consumer lane geometry
    const int ct = lane >> 3, crw = lane & 7;

    int tg = 0;
    for (int p = 0; p < NPH; p++) {
        // ======== S build: S[n][s][e''(16)] ; rows r = tid, tid+256 ========
        #pragma unroll
        for (int rr = 0; rr < 2; rr++) {
            int r = tid + rr * NTH;
            int n = r >> 4, s = r & 15;
            int e = e0 + n;
            unsigned long long a2[8];
            #pragma unroll
            for (int c = 0; c < 8; c++) a2[c] = 0ull;
            if (e < nEdges) {
                const float4* sp4 = (const float4*)sph + ((long)e * 16 + s) * 4;
                float4 sA = sp4[0], sB = sp4[1];          // k = 0..7
                const float4* mbase = (const float4*)m + ((long)e * 8) * 16 + p * 4;
                #pragma unroll
                for (int k = 0; k < 8; k++) {
                    float sv = (k < 4) ? (&sA.x)[k] : (&sB.x)[k - 4];
                    unsigned long long sk = pk2(sv, sv);
                    const float4* mrow = mbase + (long)k * 16;
                    #pragma unroll
                    for (int c4 = 0; c4 < 4; c4++) {
                        float4 mv = mrow[c4];
                        FMA2(a2[c4 * 2],     sk, pk2(mv.x, mv.y));
                        FMA2(a2[c4 * 2 + 1], sk, pk2(mv.z, mv.w));
                    }
                }
            }
            float4* Srow = S4 + n * S_F4STRIDE + s * 5;
            #pragma unroll
            for (int c4 = 0; c4 < 4; c4++) {
                float4 v;
                upk2(a2[c4 * 2], v.x, v.y);
                upk2(a2[c4 * 2 + 1], v.z, v.w);
                Srow[c4] = v;
            }
        }
        __syncthreads();

        // ======== 8 K-tiles (8 i x 16 e' each), single-barrier pipeline ========
        for (int ti = 0; ti < TPP; ti++, tg++) {
            const int buf = tg & 1;
            const uint32_t ABASE = (uint32_t)(OFF_A + buf * 16384);
            const int i0 = ti * 8;

            // ---- B prefetch chunk 0 (ks 0..3), 2 u-groups ----
            uint4 Bv[2][4];
            {
                const uint4* bp = g_Bf + ((tg * 16 + wid * 2) * 8) * 32 + lane;
                #pragma unroll
                for (int ug = 0; ug < 2; ug++)
                    #pragma unroll
                    for (int ks = 0; ks < 4; ks++) Bv[ug][ks] = bp[(ug * 8 + ks) * 32];
            }

            // ---- A-gen: thread does i = i0+2*i2+{0,1}, e'' = eh*8..+7 ----
            {
                float4 rv[2][4];
                if (e_ag < nEdges) {
                    const float4* rp = (const float4*)rbf + ((long)e_ag * 64 + i0 + 2 * i2) * 4;
                    #pragma unroll
                    for (int il = 0; il < 2; il++) {
                        rv[il][0] = rp[il * 4 + 0]; rv[il][1] = rp[il * 4 + 1];
                        rv[il][2] = rp[il * 4 + 2]; rv[il][3] = rp[il * 4 + 3];
                    }
                } else {
                    #pragma unroll
                    for (int il = 0; il < 2; il++)
                        rv[il][0] = rv[il][1] = rv[il][2] = rv[il][3] =
                            make_float4(0.f, 0.f, 0.f, 0.f);
                }
                unsigned long long a2[2][4];
                #pragma unroll
                for (int il = 0; il < 2; il++)
                    #pragma unroll
                    for (int c = 0; c < 4; c++) a2[il][c] = 0ull;
                const ulonglong2* Sn = (const ulonglong2*)(S4 + agn * S_F4STRIDE) + eh * 2;
                #pragma unroll
                for (int s = 0; s < 16; s++) {
                    ulonglong2 mv0 = Sn[s * 5];
                    ulonglong2 mv1 = Sn[s * 5 + 1];
                    #pragma unroll
                    for (int il = 0; il < 2; il++) {
                        float rb = (&rv[il][s >> 2].x)[s & 3];
                        unsigned long long rr2 = pk2(rb, rb);
                        FMA2(a2[il][0], rr2, mv0.x);
                        FMA2(a2[il][1], rr2, mv0.y);
                        FMA2(a2[il][2], rr2, mv1.x);
                        FMA2(a2[il][3], rr2, mv1.y);
                    }
                }
                #pragma unroll
                for (int il = 0; il < 2; il++) {
                    float f[8];
                    #pragma unroll
                    for (int c = 0; c < 4; c++) upk2(a2[il][c], f[2 * c], f[2 * c + 1]);
                    uint32_t hiw[4], low[4];
                    #pragma unroll
                    for (int j = 0; j < 4; j++) {
                        hiw[j] = bf2(f[2 * j + 1], f[2 * j]);
                        float g0 = __uint_as_float(hiw[j] << 16);
                        float g1 = __uint_as_float(hiw[j] & 0xFFFF0000u);
                        low[j] = bf2(f[2 * j + 1] - g1, f[2 * j] - g0);
                    }
                    int i_loc = 2 * i2 + il;
                    int kh = i_loc >> 2;
                    // single 16B unit: swizzle applies directly
                    uint32_t so = swz((uint32_t)(agn * 128 + (i_loc & 3) * 32 + eh * 16));
                    uint32_t base = ABASE + (uint32_t)(kh * 4096) + so;
                    *(uint4*)(smem + base)        = make_uint4(hiw[0], hiw[1], hiw[2], hiw[3]);
                    *(uint4*)(smem + base + 8192) = make_uint4(low[0], low[1], low[2], low[3]);
                }
            }
            __syncthreads();   // the ONLY barrier per tile: A(buf) ready

            // ---- consumer: warp wid owns u = wid*16..+15 (2 ug), all 32 n, full K ----
            #pragma unroll
            for (int half = 0; half < 2; half++) {
                #pragma unroll
                for (int kss = 0; kss < 4; kss++) {
                    const int ks = half * 4 + kss;
                    const uint32_t aregH = ABASE + (uint32_t)((ks >> 2) * 4096);
                    const uint32_t chunk = (uint32_t)((ks & 3) * 32 + (ct >> 1) * 16);
                    #pragma unroll
                    for (int mf = 0; mf < 2; mf++) {
                        uint32_t abyte = swz((uint32_t)((mf * 16 + (ct & 1) * 8 + crw) * 128)
                                             + chunk);
                        uint32_t ah0, ah1, ah2, ah3, al0, al1, al2, al3;
                        ldsm4(ah0, ah1, ah2, ah3, sb + aregH + abyte);
                        ldsm4(al0, al1, al2, al3, sb + aregH + 8192 + abyte);
                        #pragma unroll
                        for (int ug = 0; ug < 2; ug++) {
                            const uint4 B = Bv[ug][kss];
                            mma16816(acc[mf][ug], ah0, ah1, ah2, ah3, B.x, B.y);   // hi*hi
                            mma16816(acc[mf][ug], ah0, ah1, ah2, ah3, B.z, B.w);   // hi*lo
                            mma16816(acc[mf][ug], al0, al1, al2, al3, B.x, B.y);   // lo*hi
                        }
                    }
                }
                // refill Bv with chunk 1 (ks 4..7) after first half consumed
                if (half == 0) {
                    const uint4* bp = g_Bf + ((tg * 16 + wid * 2) * 8 + 4) * 32 + lane;
                    #pragma unroll
                    for (int ug = 0; ug < 2; ug++)
                        #pragma unroll
                        for (int ks = 0; ks < 4; ks++) Bv[ug][ks] = bp[(ug * 8 + ks) * 32];
                }
            }
        }
    }

    // ======== epilogue (registers only) ========
    {
        const int gid = lane >> 2, tig = lane & 3;
        #pragma unroll
        for (int mf = 0; mf < 2; mf++) {
            int e1 = e0 + mf * 16 + gid;
            int e2 = e1 + 8;
            #pragma unroll
            for (int ug = 0; ug < 2; ug++) {
                int u = wid * 16 + ug * 8 + tig * 2;
                if (e1 < nEdges)
                    *(float2*)(out + (long)e1 * 128 + u) =
                        make_float2(acc[mf][ug][0], acc[mf][ug][1]);
                if (e2 < nEdges)
                    *(float2*)(out + (long)e2 * 128 + u) =
                        make_float2(acc[mf][ug][2], acc[mf][ug][3]);
            }
        }
    }
}

extern "C" void kernel_launch(void* const* d_in, const int* in_sizes, int n_in,
                              void* d_out, int out_size)
{
    const float* rbf = (const float*)d_in[0];
    const float* sph = (const float*)d_in[1];
    const float* m   = (const float*)d_in[2];
    const float* W   = (const float*)d_in[3];
    float* out = (float*)d_out;

    int nEdges = in_sizes[0] / (64 * 16);   // 50000

    cudaFuncSetAttribute(eib_mma, cudaFuncAttributeMaxDynamicSharedMemorySize, SMEM_BYTES);

    prep_B<<<dim3(NTILES, 2), 128>>>(W);
    int grid = (nEdges + EPC - 1) / EPC;    // 1563
    eib_mma<<<grid, NTH, SMEM_BYTES>>>(rbf, sph, m, out, nEdges);
}

// round 15
// speedup vs baseline: 1.4739x; 1.0550x over previous
#include <cuda_runtime.h>
#include <cuda_bf16.h>
#include <cstdint>

#define EPC     32
#define NTH     256
#define NPH     4           // e'-phases (16 e' each)
#define TPP     4           // tiles per phase; i-block 16, K-tile = 256
#define NPTILES 32          // prep tiles (i-block 8), unchanged layout

// smem layout (bytes)
#define OFF_S   0                   // 32 n * 81 float4 = 41472
#define S_F4STRIDE 81
#define OFF_A   41472               // 2 bufs x 32768: [hi: kq0..3 x 4K][lo: kq0..3 x 4K]
#define SMEM_BYTES 107008

// B fragments, mma-ready per-lane order: [ptile(32)][g(16 u8-groups)][ks(8)][lane(32)]
// uint4 = {bh0, bh1, bl0, bl1}
__device__ __align__(16) uint4 g_Bf[NPTILES * 16 * 8 * 32];

__host__ __device__ __forceinline__ uint32_t swz(uint32_t o) { return o ^ ((o >> 3) & 0x70u); }

__device__ __forceinline__ uint32_t smem_u32(const void* p) {
    uint32_t a;
    asm("{ .reg .u64 t; cvta.to.shared.u64 t, %1; cvt.u32.u64 %0, t; }" : "=r"(a) : "l"(p));
    return a;
}
__device__ __forceinline__ unsigned long long pk2(float x, float y) {
    unsigned long long u; asm("mov.b64 %0, {%1,%2};" : "=l"(u) : "f"(x), "f"(y)); return u;
}
__device__ __forceinline__ void upk2(unsigned long long u, float& x, float& y) {
    asm("mov.b64 {%0,%1}, %2;" : "=f"(x), "=f"(y) : "l"(u));
}
#define FMA2(d, a, b) asm("fma.rn.f32x2 %0, %1, %2, %0;" : "+l"(d) : "l"(a), "l"(b))

__device__ __forceinline__ void ldsm4(uint32_t& r0, uint32_t& r1, uint32_t& r2, uint32_t& r3,
                                      uint32_t addr) {
    asm volatile("ldmatrix.sync.aligned.m8n8.x4.shared.b16 {%0,%1,%2,%3}, [%4];"
                 : "=r"(r0), "=r"(r1), "=r"(r2), "=r"(r3) : "r"(addr));
}
__device__ __forceinline__ void mma16816(float* c, uint32_t a0, uint32_t a1, uint32_t a2,
                                         uint32_t a3, uint32_t b0, uint32_t b1) {
    asm volatile("mma.sync.aligned.m16n8k16.row.col.f32.bf16.bf16.f32 "
                 "{%0,%1,%2,%3}, {%4,%5,%6,%7}, {%8,%9}, {%0,%1,%2,%3};"
                 : "+f"(c[0]), "+f"(c[1]), "+f"(c[2]), "+f"(c[3])
                 : "r"(a0), "r"(a1), "r"(a2), "r"(a3), "r"(b0), "r"(b1));
}
__device__ __forceinline__ uint32_t bf2(float hi, float lo) {
    uint32_t w;
    asm("cvt.rn.bf16x2.f32 %0, %1, %2;" : "=r"(w) : "f"(hi), "f"(lo));
    return w;
}

// ---------- prep: self-calibrating B fragment factory (R13/R14-validated, unchanged) ----------
__global__ void prep_B(const float* __restrict__ W) {
    __shared__ __align__(16) char bs[32768];     // [hi 16K][lo 16K], 128 u-rows x 128B
    const int tile = blockIdx.x, kh = blockIdx.y;
    const int p = tile >> 3, ti = tile & 7;
    const int tid = threadIdx.x;                 // 128 threads

    for (int j = tid; j < 128 * 32; j += 128) {
        int u = j >> 5, kp = j & 31;
        uint32_t hi = 0, lo = 0;
        #pragma unroll
        for (int d = 0; d < 2; d++) {
            int kk = kh * 64 + kp * 2 + d;       // kk = i_local*16 + e''
            int i = ti * 8 + (kk >> 4);
            int e = p * 16 + (kk & 15);
            float v = W[((e << 6) + i) * 128 + u];
            __nv_bfloat16 h = __float2bfloat16_rn(v);
            __nv_bfloat16 l = __float2bfloat16_rn(v - __bfloat162float(h));
            hi |= (uint32_t)(*(unsigned short*)&h) << (16 * d);
            lo |= (uint32_t)(*(unsigned short*)&l) << (16 * d);
        }
        uint32_t pos = swz((uint32_t)(u * 128 + kp * 4));
        *(uint32_t*)(bs + pos) = hi;
        *(uint32_t*)(bs + 16384 + pos) = lo;
    }
    __syncthreads();

    const int wn = tid >> 5, lane = tid & 31;
    const uint32_t sbb = smem_u32(bs);
    const int t = lane >> 3, rw = lane & 7;
    const int urow0 = wn * 32 + (t & 1) * 8 + rw;
    for (int ks = 0; ks < 4; ks++) {
        uint32_t chunk = (uint32_t)(ks * 32 + (t >> 1) * 16);
        uint32_t b0byte = swz((uint32_t)(urow0 * 128) + chunk);
        uint32_t b1byte = swz((uint32_t)((urow0 + 16) * 128) + chunk);
        uint32_t bh[8], bl[8];
        ldsm4(bh[0], bh[1], bh[2], bh[3], sbb + b0byte);
        ldsm4(bh[4], bh[5], bh[6], bh[7], sbb + b1byte);
        ldsm4(bl[0], bl[1], bl[2], bl[3], sbb + 16384 + b0byte);
        ldsm4(bl[4], bl[5], bl[6], bl[7], sbb + 16384 + b1byte);
        #pragma unroll
        for (int ub = 0; ub < 4; ub++) {
            int base = (ub >> 1) * 4 + (ub & 1);
            int g = wn * 4 + ub;                 // u8-group: u = g*8..g*8+7
            int oidx = (((tile * 16 + g) * 8) + (kh * 4 + ks)) * 32 + lane;
            g_Bf[oidx] = make_uint4(bh[base], bh[base + 2], bl[base], bl[base + 2]);
        }
    }
}

// ---------- main ----------
__global__ __launch_bounds__(NTH, 2)
void eib_mma(const float* __restrict__ rbf,   // [NE][64][16]
             const float* __restrict__ sph,   // [NE][16][16]
             const float* __restrict__ m,     // [NE*8][64]
             float* __restrict__ out,         // [NE][128]
             int nEdges)
{
    extern __shared__ char smem[];
    const uint32_t sb = smem_u32(smem);
    float4* S4 = (float4*)smem;
    const int tid = threadIdx.x, wid = tid >> 5, lane = tid & 31;
    const int e0 = blockIdx.x * EPC;

    // consumer warp roles: uq = u-quarter (32 u), kh = K-half (8 of 16 ks)
    const int uq = wid & 3, khc = wid >> 2;

    float acc[2][4][4];                            // [mf 16n][ug 8u][frag]
    #pragma unroll
    for (int mf = 0; mf < 2; mf++)
        #pragma unroll
        for (int ug = 0; ug < 4; ug++)
            #pragma unroll
            for (int c = 0; c < 4; c++) acc[mf][ug][c] = 0.f;

    // A-gen mapping: thread = (agn edge-row, q4 i-quad, eh e'-half)
    const int agn = tid >> 3;                      // 0..31
    const int q4 = tid & 3, eh = (tid >> 2) & 1;
    const int e_ag = e0 + agn;
    // consumer lane geometry
    const int ct = lane >> 3, crw = lane & 7;

    for (int p = 0; p < NPH; p++) {
        // ======== S build: S[n][s][e''(16)] ; rows r = tid, tid+256 (R14-verbatim) ========
        #pragma unroll
        for (int rr = 0; rr < 2; rr++) {
            int r = tid + rr * NTH;
            int n = r >> 4, s = r & 15;
            int e = e0 + n;
            unsigned long long a2[8];
            #pragma unroll
            for (int c = 0; c < 8; c++) a2[c] = 0ull;
            if (e < nEdges) {
                const float4* sp4 = (const float4*)sph + ((long)e * 16 + s) * 4;
                float4 sA = sp4[0], sB = sp4[1];          // k = 0..7
                const float4* mbase = (const float4*)m + ((long)e * 8) * 16 + p * 4;
                #pragma unroll
                for (int k = 0; k < 8; k++) {
                    float sv = (k < 4) ? (&sA.x)[k] : (&sB.x)[k - 4];
                    unsigned long long sk = pk2(sv, sv);
                    const float4* mrow = mbase + (long)k * 16;
                    #pragma unroll
                    for (int c4 = 0; c4 < 4; c4++) {
                        float4 mv = mrow[c4];
                        FMA2(a2[c4 * 2],     sk, pk2(mv.x, mv.y));
                        FMA2(a2[c4 * 2 + 1], sk, pk2(mv.z, mv.w));
                    }
                }
            }
            float4* Srow = S4 + n * S_F4STRIDE + s * 5;
            #pragma unroll
            for (int c4 = 0; c4 < 4; c4++) {
                float4 v;
                upk2(a2[c4 * 2], v.x, v.y);
                upk2(a2[c4 * 2 + 1], v.z, v.w);
                Srow[c4] = v;
            }
        }
        __syncthreads();

        // ======== 4 K-tiles (16 i x 16 e' each), single-barrier pipeline ========
        for (int ti = 0; ti < TPP; ti++) {
            const int tg = p * TPP + ti;
            const int buf = tg & 1;
            const uint32_t ABASE = (uint32_t)(OFF_A + buf * 32768);
            const int i0 = ti * 16;
            const int pt_base = p * 8 + ti * 2;    // prep-tile pair for this K-tile

            // ---- A-gen: thread does i = i0 + q4*4 + il (il 0..3), e'' = eh*8..+7 ----
            {
                unsigned long long a2[4][4];
                #pragma unroll
                for (int il = 0; il < 4; il++)
                    #pragma unroll
                    for (int c = 0; c < 4; c++) a2[il][c] = 0ull;
                const ulonglong2* Sn = (const ulonglong2*)(S4 + agn * S_F4STRIDE) + eh * 2;
                const float4* rbase = (const float4*)rbf + ((long)e_ag * 64 + i0 + q4 * 4) * 4;
                const bool inb = (e_ag < nEdges);
                #pragma unroll
                for (int sc = 0; sc < 4; sc++) {
                    float4 rv[4];
                    #pragma unroll
                    for (int il = 0; il < 4; il++)
                        rv[il] = inb ? rbase[il * 4 + sc] : make_float4(0.f, 0.f, 0.f, 0.f);
                    #pragma unroll
                    for (int s4 = 0; s4 < 4; s4++) {
                        int s = sc * 4 + s4;
                        ulonglong2 mv0 = Sn[s * 5];
                        ulonglong2 mv1 = Sn[s * 5 + 1];
                        #pragma unroll
                        for (int il = 0; il < 4; il++) {
                            float rb = (&rv[il].x)[s4];
                            unsigned long long rr2 = pk2(rb, rb);
                            FMA2(a2[il][0], rr2, mv0.x);
                            FMA2(a2[il][1], rr2, mv0.y);
                            FMA2(a2[il][2], rr2, mv1.x);
                            FMA2(a2[il][3], rr2, mv1.y);
                        }
                    }
                }
                // convert + store: i_loc = q4*4+il -> kq = q4 chunk, row offset (il)*32 + eh*16
                #pragma unroll
                for (int il = 0; il < 4; il++) {
                    float f[8];
                    #pragma unroll
                    for (int c = 0; c < 4; c++) upk2(a2[il][c], f[2 * c], f[2 * c + 1]);
                    uint32_t hiw[4], low[4];
                    #pragma unroll
                    for (int j = 0; j < 4; j++) {
                        hiw[j] = bf2(f[2 * j + 1], f[2 * j]);
                        float g0 = __uint_as_float(hiw[j] << 16);
                        float g1 = __uint_as_float(hiw[j] & 0xFFFF0000u);
                        low[j] = bf2(f[2 * j + 1] - g1, f[2 * j] - g0);
                    }
                    uint32_t so = swz((uint32_t)(agn * 128 + il * 32 + eh * 16));
                    uint32_t base = ABASE + (uint32_t)(q4 * 4096) + so;
                    *(uint4*)(smem + base)         = make_uint4(hiw[0], hiw[1], hiw[2], hiw[3]);
                    *(uint4*)(smem + base + 16384) = make_uint4(low[0], low[1], low[2], low[3]);
                }
            }

            // ---- B prefetch ks=0 of this warp's K-half (latency hides under barrier) ----
            uint4 Bv[2][4];
            {
                int ksg = khc * 8;
                const uint4* bp = g_Bf
                    + (((pt_base + (ksg >> 3)) * 16 + uq * 4) * 8 + (ksg & 7)) * 32 + lane;
                #pragma unroll
                for (int ug = 0; ug < 4; ug++) Bv[0][ug] = bp[ug * 8 * 32];
            }
            __syncthreads();   // the ONLY barrier per tile: A(buf) ready

            // ---- consumer: warp (uq, khc): u = uq*32..+31, ks = khc*8..+7, all 32 n ----
            #pragma unroll
            for (int ks = 0; ks < 8; ks++) {
                const int ksg = khc * 8 + ks;
                if (ks < 7) {   // rolling prefetch of next ks
                    int ksn = ksg + 1;
                    const uint4* bp = g_Bf
                        + (((pt_base + (ksn >> 3)) * 16 + uq * 4) * 8 + (ksn & 7)) * 32 + lane;
                    #pragma unroll
                    for (int ug = 0; ug < 4; ug++) Bv[(ks + 1) & 1][ug] = bp[ug * 8 * 32];
                }
                const uint32_t areg = ABASE + (uint32_t)((ksg >> 2) * 4096);
                const uint32_t chunk = (uint32_t)((ksg & 3) * 32 + (ct >> 1) * 16);
                #pragma unroll
                for (int mf = 0; mf < 2; mf++) {
                    uint32_t abyte = swz((uint32_t)((mf * 16 + (ct & 1) * 8 + crw) * 128) + chunk);
                    uint32_t ah0, ah1, ah2, ah3, al0, al1, al2, al3;
                    ldsm4(ah0, ah1, ah2, ah3, sb + areg + abyte);
                    ldsm4(al0, al1, al2, al3, sb + areg + 16384 + abyte);
                    #pragma unroll
                    for (int ug = 0; ug < 4; ug++) {
                        const uint4 B = Bv[ks & 1][ug];
                        mma16816(acc[mf][ug], ah0, ah1, ah2, ah3, B.x, B.y);   // hi*hi
                        mma16816(acc[mf][ug], ah0, ah1, ah2, ah3, B.z, B.w);   // hi*lo
                        mma16816(acc[mf][ug], al0, al1, al2, al3, B.x, B.y);   // lo*hi
                    }
                }
            }
        }
    }

    // ======== kh-reduction + epilogue ========
    __syncthreads();                                // all tiles done; S region reusable
    if (khc == 1) {
        #pragma unroll
        for (int mf = 0; mf < 2; mf++)
            #pragma unroll
            for (int ug = 0; ug < 4; ug++)
                *(float4*)(smem + (uq * 8 + mf * 4 + ug) * 512 + lane * 16) =
                    make_float4(acc[mf][ug][0], acc[mf][ug][1], acc[mf][ug][2], acc[mf][ug][3]);
    }
    __syncthreads();
    if (khc == 0) {
        const int gid = lane >> 2, tig = lane & 3;
        #pragma unroll
        for (int mf = 0; mf < 2; mf++) {
            int e1 = e0 + mf * 16 + gid;
            int e2 = e1 + 8;
            #pragma unroll
            for (int ug = 0; ug < 4; ug++) {
                float4 o = *(float4*)(smem + (uq * 8 + mf * 4 + ug) * 512 + lane * 16);
                int u = uq * 32 + ug * 8 + tig * 2;
                if (e1 < nEdges)
                    *(float2*)(out + (long)e1 * 128 + u) =
                        make_float2(acc[mf][ug][0] + o.x, acc[mf][ug][1] + o.y);
                if (e2 < nEdges)
                    *(float2*)(out + (long)e2 * 128 + u) =
                        make_float2(acc[mf][ug][2] + o.z, acc[mf][ug][3] + o.w);
            }
        }
    }
}

extern "C" void kernel_launch(void* const* d_in, const int* in_sizes, int n_in,
                              void* d_out, int out_size)
{
    const float* rbf = (const float*)d_in[0];
    const float* sph = (const float*)d_in[1];
    const float* m   = (const float*)d_in[2];
    const float* W   = (const float*)d_in[3];
    float* out = (float*)d_out;

    int nEdges = in_sizes[0] / (64 * 16);   // 50000

    cudaFuncSetAttribute(eib_mma, cudaFuncAttributeMaxDynamicSharedMemorySize, SMEM_BYTES);

    prep_B<<<dim3(NPTILES, 2), 128>>>(W);
    int grid = (nEdges + EPC - 1) / EPC;    // 1563
    eib_mma<<<grid, NTH, SMEM_BYTES>>>(rbf, sph, m, out, nEdges);
}

// round 17
// speedup vs baseline: 1.4865x; 1.0086x over previous
#include <cuda_runtime.h>
#include <cuda_bf16.h>
#include <cstdint>

#define EPC     32
#define NTH     256
#define NPH     4           // e'-phases (16 e' each)
#define TPP     4           // tiles per phase; i-block 16, K-tile = 256
#define NPTILES 32          // prep tiles (i-block 8), unchanged layout
#define NEB     1563        // edge blocks (50000/32 rounded up)

// smem layout (bytes)
// S: two e'-half blocks; addr(n,s,eh,c) = eh*16960 + n*528 + s*32 + c*16
//   bank-groups: n -> +1, eh -> +4, conflict-free for A-gen reads
#define S_EH_STRIDE 16960
#define S_N_STRIDE  528
#define OFF_A   33920               // 2 bufs x 32768: [hi: kq0..3 x 4K][lo: kq0..3 x 4K]
#define SMEM_BYTES 99456

// B fragments, mma-ready per-lane order: [ptile(32)][g(16 u8-groups)][ks(8)][lane(32)]
__device__ __align__(16) uint4 g_Bf[NPTILES * 16 * 8 * 32];
// transposed rbf: [eb][ti(4)][il(4)][sc(4)][n(32)][q4(4)] float4 units, zero-filled OOB
__device__ float4 g_T[(long)NEB * 8192];

__host__ __device__ __forceinline__ uint32_t swz(uint32_t o) { return o ^ ((o >> 3) & 0x70u); }

__device__ __forceinline__ uint32_t smem_u32(const void* p) {
    uint32_t a;
    asm("{ .reg .u64 t; cvta.to.shared.u64 t, %1; cvt.u32.u64 %0, t; }" : "=r"(a) : "l"(p));
    return a;
}
__device__ __forceinline__ unsigned long long pk2(float x, float y) {
    unsigned long long u; asm("mov.b64 %0, {%1,%2};" : "=l"(u) : "f"(x), "f"(y)); return u;
}
__device__ __forceinline__ void upk2(unsigned long long u, float& x, float& y) {
    asm("mov.b64 {%0,%1}, %2;" : "=f"(x), "=f"(y) : "l"(u));
}
#define FMA2(d, a, b) asm("fma.rn.f32x2 %0, %1, %2, %0;" : "+l"(d) : "l"(a), "l"(b))

__device__ __forceinline__ void ldsm4(uint32_t& r0, uint32_t& r1, uint32_t& r2, uint32_t& r3,
                                      uint32_t addr) {
    asm volatile("ldmatrix.sync.aligned.m8n8.x4.shared.b16 {%0,%1,%2,%3}, [%4];"
                 : "=r"(r0), "=r"(r1), "=r"(r2), "=r"(r3) : "r"(addr));
}
__device__ __forceinline__ void mma16816(float* c, uint32_t a0, uint32_t a1, uint32_t a2,
                                         uint32_t a3, uint32_t b0, uint32_t b1) {
    asm volatile("mma.sync.aligned.m16n8k16.row.col.f32.bf16.bf16.f32 "
                 "{%0,%1,%2,%3}, {%4,%5,%6,%7}, {%8,%9}, {%0,%1,%2,%3};"
                 : "+f"(c[0]), "+f"(c[1]), "+f"(c[2]), "+f"(c[3])
                 : "r"(a0), "r"(a1), "r"(a2), "r"(a3), "r"(b0), "r"(b1));
}
__device__ __forceinline__ uint32_t bf2(float hi, float lo) {
    uint32_t w;
    asm("cvt.rn.bf16x2.f32 %0, %1, %2;" : "=r"(w) : "f"(hi), "f"(lo));
    return w;
}

// ---------- prep: B fragment factory (R13/14/15-validated, unchanged) ----------
__global__ void prep_B(const float* __restrict__ W) {
    __shared__ __align__(16) char bs[32768];
    const int tile = blockIdx.x, kh = blockIdx.y;
    const int p = tile >> 3, ti = tile & 7;
    const int tid = threadIdx.x;

    for (int j = tid; j < 128 * 32; j += 128) {
        int u = j >> 5, kp = j & 31;
        uint32_t hi = 0, lo = 0;
        #pragma unroll
        for (int d = 0; d < 2; d++) {
            int kk = kh * 64 + kp * 2 + d;
            int i = ti * 8 + (kk >> 4);
            int e = p * 16 + (kk & 15);
            float v = W[((e << 6) + i) * 128 + u];
            __nv_bfloat16 h = __float2bfloat16_rn(v);
            __nv_bfloat16 l = __float2bfloat16_rn(v - __bfloat162float(h));
            hi |= (uint32_t)(*(unsigned short*)&h) << (16 * d);
            lo |= (uint32_t)(*(unsigned short*)&l) << (16 * d);
        }
        uint32_t pos = swz((uint32_t)(u * 128 + kp * 4));
        *(uint32_t*)(bs + pos) = hi;
        *(uint32_t*)(bs + 16384 + pos) = lo;
    }
    __syncthreads();

    const int wn = tid >> 5, lane = tid & 31;
    const uint32_t sbb = smem_u32(bs);
    const int t = lane >> 3, rw = lane & 7;
    const int urow0 = wn * 32 + (t & 1) * 8 + rw;
    for (int ks = 0; ks < 4; ks++) {
        uint32_t chunk = (uint32_t)(ks * 32 + (t >> 1) * 16);
        uint32_t b0byte = swz((uint32_t)(urow0 * 128) + chunk);
        uint32_t b1byte = swz((uint32_t)((urow0 + 16) * 128) + chunk);
        uint32_t bh[8], bl[8];
        ldsm4(bh[0], bh[1], bh[2], bh[3], sbb + b0byte);
        ldsm4(bh[4], bh[5], bh[6], bh[7], sbb + b1byte);
        ldsm4(bl[0], bl[1], bl[2], bl[3], sbb + 16384 + b0byte);
        ldsm4(bl[4], bl[5], bl[6], bl[7], sbb + 16384 + b1byte);
        #pragma unroll
        for (int ub = 0; ub < 4; ub++) {
            int base = (ub >> 1) * 4 + (ub & 1);
            int g = wn * 4 + ub;
            int oidx = (((tile * 16 + g) * 8) + (kh * 4 + ks)) * 32 + lane;
            g_Bf[oidx] = make_uint4(bh[base], bh[base + 2], bl[base], bl[base + 2]);
        }
    }
}

// ---------- prep: rbf transpose for coalesced A-gen loads ----------
// out o = (((ti*4+il)*4+sc)*32 + n)*4 + q4 ; i = ti*16 + q4*4 + il ; e = eb*32+n
__global__ void prep_T(const float* __restrict__ rbf, int nEdges) {
    const int eb = blockIdx.x;
    const float4* r4 = (const float4*)rbf;
    for (int o = threadIdx.x; o < 8192; o += 256) {
        int q4 = o & 3, nn = (o >> 2) & 31, sc = (o >> 7) & 3, il = (o >> 9) & 3, ti = o >> 11;
        int e = eb * 32 + nn;
        int i = ti * 16 + q4 * 4 + il;
        float4 v = make_float4(0.f, 0.f, 0.f, 0.f);
        if (e < nEdges) v = r4[((long)e * 64 + i) * 4 + sc];
        g_T[(long)eb * 8192 + o] = v;
    }
}

// ---------- main ----------
__global__ __launch_bounds__(NTH, 2)
void eib_mma(const float* __restrict__ sph,   // [NE][16][16]
             const float* __restrict__ m,     // [NE*8][64]
             float* __restrict__ out,         // [NE][128]
             int nEdges)
{
    extern __shared__ char smem[];
    const uint32_t sb = smem_u32(smem);
    const int tid = threadIdx.x, wid = tid >> 5, lane = tid & 31;
    const int e0 = blockIdx.x * EPC;

    const int uq = wid & 3, khc = wid >> 2;

    float acc[2][4][4];
    #pragma unroll
    for (int mf = 0; mf < 2; mf++)
        #pragma unroll
        for (int ug = 0; ug < 4; ug++)
            #pragma unroll
            for (int c = 0; c < 4; c++) acc[mf][ug][c] = 0.f;

    // A-gen mapping: thread = (agn edge-row, q4 i-quad, eh e'-half)
    const int agn = tid >> 3;
    const int q4 = tid & 3, eh = (tid >> 2) & 1;
    const int ct = lane >> 3, crw = lane & 7;
    const float4* Tb = g_T + (long)blockIdx.x * 8192 + (agn * 4 + q4);

    for (int p = 0; p < NPH; p++) {
        // ======== S build (math R15-verbatim; new conflict-free store layout) ========
        #pragma unroll
        for (int rr = 0; rr < 2; rr++) {
            int r = tid + rr * NTH;
            int n = r >> 4, s = r & 15;
            int e = e0 + n;
            unsigned long long a2[8];
            #pragma unroll
            for (int c = 0; c < 8; c++) a2[c] = 0ull;
            if (e < nEdges) {
                const float4* sp4 = (const float4*)sph + ((long)e * 16 + s) * 4;
                float4 sA = sp4[0], sB = sp4[1];
                const float4* mbase = (const float4*)m + ((long)e * 8) * 16 + p * 4;
                #pragma unroll
                for (int k = 0; k < 8; k++) {
                    float sv = (k < 4) ? (&sA.x)[k] : (&sB.x)[k - 4];
                    unsigned long long sk = pk2(sv, sv);
                    const float4* mrow = mbase + (long)k * 16;
                    #pragma unroll
                    for (int c4 = 0; c4 < 4; c4++) {
                        float4 mv = mrow[c4];
                        FMA2(a2[c4 * 2],     sk, pk2(mv.x, mv.y));
                        FMA2(a2[c4 * 2 + 1], sk, pk2(mv.z, mv.w));
                    }
                }
            }
            #pragma unroll
            for (int c4 = 0; c4 < 4; c4++) {
                float4 v;
                upk2(a2[c4 * 2], v.x, v.y);
                upk2(a2[c4 * 2 + 1], v.z, v.w);
                uint32_t so = (uint32_t)((c4 >> 1) * S_EH_STRIDE + n * S_N_STRIDE
                                         + s * 32 + (c4 & 1) * 16);
                *(float4*)(smem + so) = v;
            }
        }
        __syncthreads();

        // ======== 4 K-tiles (16 i x 16 e' each), single-barrier pipeline ========
        for (int ti = 0; ti < TPP; ti++) {
            const int tg = p * TPP + ti;
            const int buf = tg & 1;
            const uint32_t ABASE = (uint32_t)(OFF_A + buf * 32768);
            const int pt_base = p * 8 + ti * 2;

            // ---- A-gen: i = ti*16 + q4*4 + il, e'' = eh*8..+7 ----
            {
                unsigned long long a2[4][4];
                #pragma unroll
                for (int il = 0; il < 4; il++)
                    #pragma unroll
                    for (int c = 0; c < 4; c++) a2[il][c] = 0ull;
                const char* Sn = smem + eh * S_EH_STRIDE + agn * S_N_STRIDE;
                #pragma unroll
                for (int sc = 0; sc < 4; sc++) {
                    float4 rv[4];
                    #pragma unroll
                    for (int il = 0; il < 4; il++)
                        rv[il] = Tb[((ti * 4 + il) * 4 + sc) * 128];
                    #pragma unroll
                    for (int s4 = 0; s4 < 4; s4++) {
                        int s = sc * 4 + s4;
                        ulonglong2 mv0 = *(const ulonglong2*)(Sn + s * 32);
                        ulonglong2 mv1 = *(const ulonglong2*)(Sn + s * 32 + 16);
                        #pragma unroll
                        for (int il = 0; il < 4; il++) {
                            float rb = (&rv[il].x)[s4];
                            unsigned long long rr2 = pk2(rb, rb);
                            FMA2(a2[il][0], rr2, mv0.x);
                            FMA2(a2[il][1], rr2, mv0.y);
                            FMA2(a2[il][2], rr2, mv1.x);
                            FMA2(a2[il][3], rr2, mv1.y);
                        }
                    }
                }
                #pragma unroll
                for (int il = 0; il < 4; il++) {
                    float f[8];
                    #pragma unroll
                    for (int c = 0; c < 4; c++) upk2(a2[il][c], f[2 * c], f[2 * c + 1]);
                    uint32_t hiw[4], low[4];
                    #pragma unroll
                    for (int j = 0; j < 4; j++) {
                        hiw[j] = bf2(f[2 * j + 1], f[2 * j]);
                        float g0 = __uint_as_float(hiw[j] << 16);
                        float g1 = __uint_as_float(hiw[j] & 0xFFFF0000u);
                        low[j] = bf2(f[2 * j + 1] - g1, f[2 * j] - g0);
                    }
                    uint32_t so = swz((uint32_t)(agn * 128 + il * 32 + eh * 16));
                    uint32_t base = ABASE + (uint32_t)(q4 * 4096) + so;
                    *(uint4*)(smem + base)         = make_uint4(hiw[0], hiw[1], hiw[2], hiw[3]);
                    *(uint4*)(smem + base + 16384) = make_uint4(low[0], low[1], low[2], low[3]);
                }
            }

            // ---- B prefetch ks=0 of this warp's K-half ----
            uint4 Bv[2][4];
            {
                int ksg = khc * 8;
                const uint4* bp = g_Bf
                    + (((pt_base + (ksg >> 3)) * 16 + uq * 4) * 8 + (ksg & 7)) * 32 + lane;
                #pragma unroll
                for (int ug = 0; ug < 4; ug++) Bv[0][ug] = bp[ug * 8 * 32];
            }
            __syncthreads();   // the ONLY barrier per tile: A(buf) ready

            // ---- consumer (R15-verbatim) ----
            #pragma unroll
            for (int ks = 0; ks < 8; ks++) {
                const int ksg = khc * 8 + ks;
                if (ks < 7) {
                    int ksn = ksg + 1;
                    const uint4* bp = g_Bf
                        + (((pt_base + (ksn >> 3)) * 16 + uq * 4) * 8 + (ksn & 7)) * 32 + lane;
                    #pragma unroll
                    for (int ug = 0; ug < 4; ug++) Bv[(ks + 1) & 1][ug] = bp[ug * 8 * 32];
                }
                const uint32_t areg = ABASE + (uint32_t)((ksg >> 2) * 4096);
                const uint32_t chunk = (uint32_t)((ksg & 3) * 32 + (ct >> 1) * 16);
                #pragma unroll
                for (int mf = 0; mf < 2; mf++) {
                    uint32_t abyte = swz((uint32_t)((mf * 16 + (ct & 1) * 8 + crw) * 128) + chunk);
                    uint32_t ah0, ah1, ah2, ah3, al0, al1, al2, al3;
                    ldsm4(ah0, ah1, ah2, ah3, sb + areg + abyte);
                    ldsm4(al0, al1, al2, al3, sb + areg + 16384 + abyte);
                    #pragma unroll
                    for (int ug = 0; ug < 4; ug++) {
                        const uint4 B = Bv[ks & 1][ug];
                        mma16816(acc[mf][ug], ah0, ah1, ah2, ah3, B.x, B.y);
                        mma16816(acc[mf][ug], ah0, ah1, ah2, ah3, B.z, B.w);
                        mma16816(acc[mf][ug], al0, al1, al2, al3, B.x, B.y);
                    }
                }
            }
        }
    }

    // ======== kh-reduction + epilogue (reuses dead S region) ========
    __syncthreads();
    if (khc == 1) {
        #pragma unroll
        for (int mf = 0; mf < 2; mf++)
            #pragma unroll
            for (int ug = 0; ug < 4; ug++)
                *(float4*)(smem + (uq * 8 + mf * 4 + ug) * 512 + lane * 16) =
                    make_float4(acc[mf][ug][0], acc[mf][ug][1], acc[mf][ug][2], acc[mf][ug][3]);
    }
    __syncthreads();
    if (khc == 0) {
        const int gid = lane >> 2, tig = lane & 3;
        #pragma unroll
        for (int mf = 0; mf < 2; mf++) {
            int e1 = e0 + mf * 16 + gid;
            int e2 = e1 + 8;
            #pragma unroll
            for (int ug = 0; ug < 4; ug++) {
                float4 o = *(float4*)(smem + (uq * 8 + mf * 4 + ug) * 512 + lane * 16);
                int u = uq * 32 + ug * 8 + tig * 2;
                if (e1 < nEdges)
                    *(float2*)(out + (long)e1 * 128 + u) =
                        make_float2(acc[mf][ug][0] + o.x, acc[mf][ug][1] + o.y);
                if (e2 < nEdges)
                    *(float2*)(out + (long)e2 * 128 + u) =
                        make_float2(acc[mf][ug][2] + o.z, acc[mf][ug][3] + o.w);
            }
        }
    }
}

extern "C" void kernel_launch(void* const* d_in, const int* in_sizes, int n_in,
                              void* d_out, int out_size)
{
    const float* rbf = (const float*)d_in[0];
    const float* sph = (const float*)d_in[1];
    const float* m   = (const float*)d_in[2];
    const float* W   = (const float*)d_in[3];
    float* out = (float*)d_out;

    int nEdges = in_sizes[0] / (64 * 16);   // 50000
    int grid = (nEdges + EPC - 1) / EPC;    // 1563

    cudaFuncSetAttribute(eib_mma, cudaFuncAttributeMaxDynamicSharedMemorySize, SMEM_BYTES);

    prep_B<<<dim3(NPTILES, 2), 128>>>(W);
    prep_T<<<grid, 256>>>(rbf, nEdges);
    eib_mma<<<grid, NTH, SMEM_BYTES>>>(sph, m, out, nEdges);
}